// round 7
// baseline (speedup 1.0000x reference)
#include <cuda_runtime.h>

#define EMAX   2048
#define NNODES 4096
#define LWALK  8
#define HID    128
#define GPB    4      // graphs per block
#define TPB    256
#define FCAP   1024   // frontier entries per level (expected ~64 at L1, shrinking)
#define QMAX   2      // ceil(EMAX/4/TPB) staged int4 chunks per thread

struct Sh {
    int  head[NNODES];     // 16 KB: node v -> first edge k with dst[k]==v (-1 end)
    int  adj[EMAX];        //  8 KB: (src[k]<<16) | next_k  (0xFFFF = end)
    int2 fr[2][FCAP];      //  8 KB: x=(gl<<11)|start, y=(src_j<<12)|dst_j
    int  cnt[LWALK + 1];   // per-level frontier sizes
    int  sig[GPB][LWALK];
};

__global__ void __launch_bounds__(TPB, 1)
k_fused(const int* __restrict__ edge_index, const int* __restrict__ egraph,
        const float* __restrict__ W1, const float* __restrict__ b1,
        const float* __restrict__ W2, const float* __restrict__ b2,
        float* __restrict__ out, int E, int G) {
    __shared__ Sh sh;
    const int tid = threadIdx.x;
    const int g0  = blockIdx.x * GPB;
    const int w = tid >> 5, lane = tid & 31;

    // ---- Issue all global loads up front (latency hidden behind init) ----
    const int E4 = E >> 2;
    const int4* src4 = (const int4*)edge_index;
    const int4* dst4 = (const int4*)(edge_index + E);
    const int4* eg4  = (const int4*)egraph;
    int4 rs[QMAX], rd[QMAX], rg[QMAX];
#pragma unroll
    for (int c = 0; c < QMAX; c++) {
        const int q = tid + c * TPB;
        if (q < E4) { rs[c] = src4[q]; rd[c] = dst4[q]; rg[c] = eg4[q]; }
    }

    float rb1[HID / 32], rW2[HID / 32], rW1[HID / 32][LWALK];
    if (w < GPB) {
#pragma unroll
        for (int r = 0; r < HID / 32; r++) {
            const int u = lane + r * 32;
            rb1[r] = b1[u];
            rW2[r] = W2[u];
#pragma unroll
            for (int t = 0; t < LWALK; t++) rW1[r][t] = W1[t * HID + u];
        }
    }

    // ---- Phase A: init head + counters ----
    {
        int4* ph = (int4*)sh.head;
        const int4 m1 = make_int4(-1, -1, -1, -1);
        for (int v = tid; v < NNODES / 4; v += TPB) ph[v] = m1;
    }
    if (tid < GPB * LWALK) ((int*)sh.sig)[tid] = 0;
    if (tid <= LWALK) sh.cnt[tid] = 0;
    __syncthreads();

    // ---- Phase B: build in-edge lists + seed frontier, straight from regs ----
#pragma unroll
    for (int c = 0; c < QMAX; c++) {
        const int q = tid + c * TPB;
        if (q >= E4) break;
        const int i0 = q * 4;
        const int ss[4] = {rs[c].x, rs[c].y, rs[c].z, rs[c].w};
        const int dd[4] = {rd[c].x, rd[c].y, rd[c].z, rd[c].w};
        const int gg[4] = {rg[c].x, rg[c].y, rg[c].z, rg[c].w};
#pragma unroll
        for (int j = 0; j < 4; j++) {
            const int i = i0 + j;
            const int old = atomicExch(&sh.head[dd[j]], i);
            sh.adj[i] = (ss[j] << 16) | (old & 0xFFFF);
            const int gl = gg[j] - g0;
            if ((unsigned)gl < GPB) {
                const int pos = atomicAdd(&sh.cnt[0], 1);
                if (pos < FCAP)
                    sh.fr[0][pos] = make_int2((gl << 11) | i, (ss[j] << 12) | dd[j]);
            }
        }
    }
    __syncthreads();

    // ---- Phase C: warp 0 runs the level DP, lengths 1..LWALK ----
    // Successor k of edge j: dst_k==src_j (list membership) && src_k!=dst_j.
    // Next state carries (src_k, dst_k=src_j); closed when k == start edge.
    if (w == 0) {
        int n = min(sh.cnt[0], FCAP);
#pragma unroll
        for (int t = 1; t <= LWALK; t++) {
            const int p = (t - 1) & 1;
            for (int e = lane; e < n; e += 32) {
                const int2 v = sh.fr[p][e];
                const int start = v.x & 0x7FF;
                const int gl    = v.x >> 11;
                const int sj    = v.y >> 12;
                const int dj    = v.y & 0xFFF;
                for (int k = sh.head[sj]; k >= 0; ) {
                    const int a    = sh.adj[k];
                    const int srck = a >> 16;
                    if (srck != dj) {                       // non-backtracking
                        if (k == start)                     // closed walk length t
                            atomicAdd(&sh.sig[gl][t - 1], 1);
                        if (t < LWALK) {
                            const int pos = atomicAdd(&sh.cnt[t], 1);
                            if (pos < FCAP)
                                sh.fr[p ^ 1][pos] = make_int2(v.x, (srck << 12) | sj);
                        }
                    }
                    const int nk = a & 0xFFFF;
                    k = (nk == 0xFFFF) ? -1 : nk;
                }
            }
            __syncwarp();
            n = min(sh.cnt[t], FCAP);
        }
    }
    __syncthreads();

    // ---- Phase D: MLP (8 -> 128 -> 1) from prefetched registers ----
    const int g = g0 + w;
    if (w < GPB && g < G) {
        float sigf[LWALK];
#pragma unroll
        for (int t = 0; t < LWALK; t++) sigf[t] = (float)sh.sig[w][t];

        float acc = 0.0f;
#pragma unroll
        for (int r = 0; r < HID / 32; r++) {
            float s = rb1[r];
#pragma unroll
            for (int t = 0; t < LWALK; t++) s += sigf[t] * rW1[r][t];
            acc += fmaxf(s, 0.0f) * rW2[r];
        }
#pragma unroll
        for (int off = 16; off > 0; off >>= 1)
            acc += __shfl_xor_sync(0xffffffffu, acc, off);
        if (lane == 0) out[g] = acc + b2[0];
    }
}

extern "C" void kernel_launch(void* const* d_in, const int* in_sizes, int n_in,
                              void* d_out, int out_size) {
    const int*   edge_index = (const int*)d_in[0];   // (2, E)
    const int*   edge_graph = (const int*)d_in[1];   // (E,)
    const float* W1         = (const float*)d_in[2]; // (L, HID)
    const float* b1         = (const float*)d_in[3]; // (HID,)
    const float* W2         = (const float*)d_in[4]; // (HID, 1)
    const float* b2         = (const float*)d_in[5]; // (1,)
    float*       out        = (float*)d_out;         // (G,)

    const int E = in_sizes[0] / 2;
    const int G = out_size;
    const int nblocks = (G + GPB - 1) / GPB;

    k_fused<<<nblocks, TPB>>>(edge_index, edge_graph, W1, b1, W2, b2, out, E, G);
}

// round 8
// speedup vs baseline: 1.0331x; 1.0331x over previous
#include <cuda_runtime.h>

#define EMAX   2048
#define NNODES 4096
#define LWALK  8
#define HID    128
#define GPB    4      // graphs per block
#define TPB    256
#define FCAP   1024
#define E4C    (EMAX / 4)      // 512 int4 chunks
#define QMAX   (E4C / TPB)     // 2 chunks per thread, exact

struct Sh {
    int  head[NNODES];     // 16 KB: node v -> first edge k with dst[k]==v (-1 end)
    int  adj[EMAX];        //  8 KB: (src[k]<<16) | next_k  (0xFFFF = end)
    int2 fr[2][FCAP];      //  8 KB: x=(gl<<11)|start, y=(src_j<<12)|dst_j
    int  cnt[LWALK + 1];
    int  sig[GPB][LWALK];
};

__global__ void __launch_bounds__(TPB, 1)
k_fused(const int* __restrict__ edge_index, const int* __restrict__ egraph,
        const float* __restrict__ W1, const float* __restrict__ b1,
        const float* __restrict__ W2, const float* __restrict__ b2,
        float* __restrict__ out, int E, int G) {
    __shared__ Sh sh;
    const int tid = threadIdx.x;
    const int g0  = blockIdx.x * GPB;
    const int w = tid >> 5, lane = tid & 31;

    // ---- Issue all global loads up front (compile-time exact bounds) ----
    const int4* src4 = (const int4*)edge_index;
    const int4* dst4 = (const int4*)(edge_index + EMAX);
    const int4* eg4  = (const int4*)egraph;
    int4 rs[QMAX], rd[QMAX], rg[QMAX];
#pragma unroll
    for (int c = 0; c < QMAX; c++) {
        const int q = tid + c * TPB;
        rs[c] = src4[q]; rd[c] = dst4[q]; rg[c] = eg4[q];
    }

    float rb1[HID / 32], rW2[HID / 32], rW1[HID / 32][LWALK];
    if (w < GPB) {
#pragma unroll
        for (int r = 0; r < HID / 32; r++) {
            const int u = lane + r * 32;
            rb1[r] = b1[u];
            rW2[r] = W2[u];
#pragma unroll
            for (int t = 0; t < LWALK; t++) rW1[r][t] = W1[t * HID + u];
        }
    }

    // ---- Phase A: init head + counters ----
    {
        int4* ph = (int4*)sh.head;
        const int4 m1 = make_int4(-1, -1, -1, -1);
#pragma unroll
        for (int c = 0; c < NNODES / 4 / TPB; c++) ph[tid + c * TPB] = m1;
    }
    if (tid < GPB * LWALK) ((int*)sh.sig)[tid] = 0;
    if (tid <= LWALK) sh.cnt[tid] = 0;
    __syncthreads();

    // ---- Phase B: build in-edge lists (batched independent atomics) ----
    int olds[QMAX * 4];
#pragma unroll
    for (int c = 0; c < QMAX; c++) {
        const int i0 = (tid + c * TPB) * 4;
        olds[c * 4 + 0] = atomicExch(&sh.head[rd[c].x], i0 + 0);
        olds[c * 4 + 1] = atomicExch(&sh.head[rd[c].y], i0 + 1);
        olds[c * 4 + 2] = atomicExch(&sh.head[rd[c].z], i0 + 2);
        olds[c * 4 + 3] = atomicExch(&sh.head[rd[c].w], i0 + 3);
    }
#pragma unroll
    for (int c = 0; c < QMAX; c++) {
        const int i0 = (tid + c * TPB) * 4;
        const int ss[4] = {rs[c].x, rs[c].y, rs[c].z, rs[c].w};
#pragma unroll
        for (int j = 0; j < 4; j++)
            sh.adj[i0 + j] = (ss[j] << 16) | (olds[c * 4 + j] & 0xFFFF);
    }

    // ---- Seed frontier: warp-aggregated append ----
#pragma unroll
    for (int c = 0; c < QMAX; c++) {
        const int i0 = (tid + c * TPB) * 4;
        const int ss[4] = {rs[c].x, rs[c].y, rs[c].z, rs[c].w};
        const int dd[4] = {rd[c].x, rd[c].y, rd[c].z, rd[c].w};
        const int gg[4] = {rg[c].x, rg[c].y, rg[c].z, rg[c].w};
#pragma unroll
        for (int j = 0; j < 4; j++) {
            const int gl = gg[j] - g0;
            const bool hit = (unsigned)gl < GPB;
            const unsigned m = __ballot_sync(0xffffffffu, hit);
            if (hit) {
                int base;
                const int leader = __ffs(m) - 1;
                if (lane == leader) base = atomicAdd(&sh.cnt[0], __popc(m));
                base = __shfl_sync(m, base, leader);
                const int pos = base + __popc(m & ((1u << lane) - 1));
                if (pos < FCAP)
                    sh.fr[0][pos] = make_int2((gl << 11) | (i0 + j),
                                              (ss[j] << 12) | dd[j]);
            }
        }
    }
    __syncthreads();

    // ---- Phase C: warp 0 runs the level DP, lengths 1..LWALK ----
    // Successor k of edge j: dst_k==src_j (list membership) && src_k!=dst_j.
    if (w == 0) {
        int n = min(sh.cnt[0], FCAP);
#pragma unroll
        for (int t = 1; t <= LWALK; t++) {
            if (n == 0) break;
            const int p = (t - 1) & 1;
            for (int e = lane; e < n; e += 32) {
                const int2 v = sh.fr[p][e];
                const int start = v.x & 0x7FF;
                const int gl    = v.x >> 11;
                const int sj    = v.y >> 12;
                const int dj    = v.y & 0xFFF;
                for (int k = sh.head[sj]; k >= 0; ) {
                    const int a    = sh.adj[k];
                    const int srck = a >> 16;
                    if (srck != dj) {                       // non-backtracking
                        if (k == start)                     // closed walk length t
                            atomicAdd(&sh.sig[gl][t - 1], 1);
                        if (t < LWALK) {
                            const int pos = atomicAdd(&sh.cnt[t], 1);
                            if (pos < FCAP)
                                sh.fr[p ^ 1][pos] = make_int2(v.x, (srck << 12) | sj);
                        }
                    }
                    const int nk = a & 0xFFFF;
                    k = (nk == 0xFFFF) ? -1 : nk;
                }
            }
            __syncwarp();
            n = min(sh.cnt[t], FCAP);
        }
    }
    __syncthreads();

    // ---- Phase D: MLP (8 -> 128 -> 1) from prefetched registers ----
    const int g = g0 + w;
    if (w < GPB && g < G) {
        float sigf[LWALK];
#pragma unroll
        for (int t = 0; t < LWALK; t++) sigf[t] = (float)sh.sig[w][t];

        float acc = 0.0f;
#pragma unroll
        for (int r = 0; r < HID / 32; r++) {
            float s = rb1[r];
#pragma unroll
            for (int t = 0; t < LWALK; t++) s += sigf[t] * rW1[r][t];
            acc += fmaxf(s, 0.0f) * rW2[r];
        }
#pragma unroll
        for (int off = 16; off > 0; off >>= 1)
            acc += __shfl_xor_sync(0xffffffffu, acc, off);
        if (lane == 0) out[g] = acc + b2[0];
    }
}

extern "C" void kernel_launch(void* const* d_in, const int* in_sizes, int n_in,
                              void* d_out, int out_size) {
    const int*   edge_index = (const int*)d_in[0];   // (2, E)
    const int*   edge_graph = (const int*)d_in[1];   // (E,)
    const float* W1         = (const float*)d_in[2]; // (L, HID)
    const float* b1         = (const float*)d_in[3]; // (HID,)
    const float* W2         = (const float*)d_in[4]; // (HID, 1)
    const float* b2         = (const float*)d_in[5]; // (1,)
    float*       out        = (float*)d_out;         // (G,)

    const int E = in_sizes[0] / 2;   // == EMAX for this problem
    const int G = out_size;
    const int nblocks = (G + GPB - 1) / GPB;

    k_fused<<<nblocks, TPB>>>(edge_index, edge_graph, W1, b1, W2, b2, out, E, G);
}

// round 11
// speedup vs baseline: 1.2657x; 1.2251x over previous
#include <cuda_runtime.h>

#define EMAX   2048
#define NNODES 4096
#define LWALK  8
#define HID    128
#define GPB    4        // graphs per block, one warp each
#define TPB    512
#define FCAPG  256      // frontier entries per graph per level (expected ~10)

struct Sh {
    int  head[NNODES];            // 16 KB: node v -> first edge k with dst[k]==v (-1 end)
    int  adj[EMAX];               //  8 KB: (src[k]<<16) | next_k (0xFFFF = end)
    int2 fr[2][GPB][FCAPG];       // 16 KB: x=start edge, y=(src_j<<12)|dst_j
    int  cnt0[GPB];               // seed counts
    int  cntl[GPB][LWALK + 1];    // per-warp per-level counts
};

__global__ void __launch_bounds__(TPB, 1)
k_fused(const int* __restrict__ edge_index, const int* __restrict__ egraph,
        const float* __restrict__ W1, const float* __restrict__ b1,
        const float* __restrict__ W2, const float* __restrict__ b2,
        float* __restrict__ out, int E, int G) {
    __shared__ Sh sh;
    const int tid  = threadIdx.x;
    const int g0   = blockIdx.x * GPB;
    const int w    = tid >> 5, lane = tid & 31;

    // ---- Issue all global loads up front (one int4 per array per thread) ----
    const int4 rs = ((const int4*)edge_index)[tid];
    const int4 rd = ((const int4*)(edge_index + EMAX))[tid];
    const int4 rg = ((const int4*)egraph)[tid];

    float rb1[HID / 32], rW2[HID / 32], rW1[HID / 32][LWALK];
    if (w < GPB) {
#pragma unroll
        for (int r = 0; r < HID / 32; r++) {
            const int u = lane + r * 32;
            rb1[r] = b1[u];
            rW2[r] = W2[u];
#pragma unroll
            for (int t = 0; t < LWALK; t++) rW1[r][t] = W1[t * HID + u];
        }
    }

    // ---- Phase A: init head + counters ----
    {
        int4* ph = (int4*)sh.head;
        const int4 m1 = make_int4(-1, -1, -1, -1);
#pragma unroll
        for (int c = 0; c < NNODES / 4 / TPB; c++) ph[tid + c * TPB] = m1;
    }
    if (tid < GPB) sh.cnt0[tid] = 0;
    if (tid < GPB * (LWALK + 1)) ((int*)sh.cntl)[tid] = 0;
    __syncthreads();

    // ---- Phase B: build in-edge lists (batched atomics) + seed per-graph frontiers ----
    {
        const int i0 = tid * 4;
        int o0 = atomicExch(&sh.head[rd.x], i0 + 0);
        int o1 = atomicExch(&sh.head[rd.y], i0 + 1);
        int o2 = atomicExch(&sh.head[rd.z], i0 + 2);
        int o3 = atomicExch(&sh.head[rd.w], i0 + 3);
        sh.adj[i0 + 0] = (rs.x << 16) | (o0 & 0xFFFF);
        sh.adj[i0 + 1] = (rs.y << 16) | (o1 & 0xFFFF);
        sh.adj[i0 + 2] = (rs.z << 16) | (o2 & 0xFFFF);
        sh.adj[i0 + 3] = (rs.w << 16) | (o3 & 0xFFFF);

        const int ss[4] = {rs.x, rs.y, rs.z, rs.w};
        const int dd[4] = {rd.x, rd.y, rd.z, rd.w};
        const int gg[4] = {rg.x, rg.y, rg.z, rg.w};
#pragma unroll
        for (int j = 0; j < 4; j++) {
            const int gl = gg[j] - g0;
            if ((unsigned)gl < GPB) {
                const int pos = atomicAdd(&sh.cnt0[gl], 1);
                if (pos < FCAPG)
                    sh.fr[0][gl][pos] = make_int2(i0 + j, (ss[j] << 12) | dd[j]);
            }
        }
    }
    __syncthreads();

    // ---- Phase C+D: warps 0..3 each own one graph; warps 4..15 exit ----
    if (w >= GPB) return;
    const int g = g0 + w;
    if (g >= G) return;

    // Level DP, lengths 1..LWALK. Successor k of edge j:
    // dst_k==src_j (list membership) && src_k!=dst_j. Closed when k==start.
    int cnt[LWALK];
#pragma unroll
    for (int t = 0; t < LWALK; t++) cnt[t] = 0;

    int n = min(sh.cnt0[w], FCAPG);
#pragma unroll
    for (int t = 1; t <= LWALK; t++) {
        if (n == 0) break;
        const int p = (t - 1) & 1;
        for (int e = lane; e < n; e += 32) {
            const int2 v = sh.fr[p][w][e];
            const int start = v.x;
            const int sj    = v.y >> 12;
            const int dj    = v.y & 0xFFF;
            for (int k = sh.head[sj]; k >= 0; ) {
                const int a    = sh.adj[k];
                const int srck = a >> 16;
                if (srck != dj) {                         // non-backtracking
                    if (k == start) cnt[t - 1]++;         // closed walk length t
                    if (t < LWALK) {
                        const int pos = atomicAdd(&sh.cntl[w][t], 1);
                        if (pos < FCAPG)
                            sh.fr[p ^ 1][w][pos] = make_int2(start, (srck << 12) | sj);
                    }
                }
                const int nk = a & 0xFFFF;
                k = (nk == 0xFFFF) ? -1 : nk;
            }
        }
        __syncwarp();
        n = min(sh.cntl[w][t], FCAPG);
    }

    // Warp-reduce the 8 per-lane counters -> signature
    float sigf[LWALK];
#pragma unroll
    for (int t = 0; t < LWALK; t++) {
        int c = cnt[t];
#pragma unroll
        for (int off = 16; off > 0; off >>= 1)
            c += __shfl_xor_sync(0xffffffffu, c, off);
        sigf[t] = (float)c;
    }

    // MLP (8 -> 128 -> 1) from prefetched registers
    float acc = 0.0f;
#pragma unroll
    for (int r = 0; r < HID / 32; r++) {
        float s = rb1[r];
#pragma unroll
        for (int t = 0; t < LWALK; t++) s += sigf[t] * rW1[r][t];
        acc += fmaxf(s, 0.0f) * rW2[r];
    }
#pragma unroll
    for (int off = 16; off > 0; off >>= 1)
        acc += __shfl_xor_sync(0xffffffffu, acc, off);
    if (lane == 0) out[g] = acc + b2[0];
}

extern "C" void kernel_launch(void* const* d_in, const int* in_sizes, int n_in,
                              void* d_out, int out_size) {
    const int*   edge_index = (const int*)d_in[0];   // (2, E)
    const int*   edge_graph = (const int*)d_in[1];   // (E,)
    const float* W1         = (const float*)d_in[2]; // (L, HID)
    const float* b1         = (const float*)d_in[3]; // (HID,)
    const float* W2         = (const float*)d_in[4]; // (HID, 1)
    const float* b2         = (const float*)d_in[5]; // (1,)
    float*       out        = (float*)d_out;         // (G,)

    const int E = in_sizes[0] / 2;   // == EMAX for this problem
    const int G = out_size;
    const int nblocks = (G + GPB - 1) / GPB;

    k_fused<<<nblocks, TPB>>>(edge_index, edge_graph, W1, b1, W2, b2, out, E, G);
}